// round 12
// baseline (speedup 1.0000x reference)
#include <cuda_runtime.h>
#include <cuda_bf16.h>
#include <cstdint>

// Problem constants
#define BB      1024
#define CC      64
#define WW      40
#define NPROT   40
#define NCLS    512
#define PP      (NPROT * NCLS)   // 20480

// ---------------------------------------------------------------------------
// Scratch (device globals; no dynamic allocation)
// ---------------------------------------------------------------------------
__device__ __align__(16) __nv_bfloat16 g_xh[NPROT * BB * CC];    // [i][b][c] hi
__device__ __align__(16) __nv_bfloat16 g_xl[NPROT * BB * CC];    // [i][b][c] lo
__device__ __align__(16) __nv_bfloat16 g_ph[NPROT * NCLS * CC];  // [i][a][c] hi
__device__ __align__(16) __nv_bfloat16 g_pl[NPROT * NCLS * CC];  // [i][a][c] lo
__device__ __align__(16) float g_acc[BB * NCLS];                 // S_n(b)

// ---------------------------------------------------------------------------
// Portable helpers (compute_103-safe: ldmatrix + mma.sync + cp.async)
// ---------------------------------------------------------------------------
__device__ __forceinline__ uint32_t smem_to_u32(const void* p) {
    uint32_t a;
    asm("{ .reg .u64 t; cvta.to.shared.u64 t, %1; cvt.u32.u64 %0, t; }"
        : "=r"(a) : "l"(p));
    return a;
}

#define LDSM_X4(r, addr) \
    asm volatile("ldmatrix.sync.aligned.m8n8.x4.shared.b16 {%0,%1,%2,%3}, [%4];" \
                 : "=r"((r)[0]), "=r"((r)[1]), "=r"((r)[2]), "=r"((r)[3]) \
                 : "r"(addr))

__device__ __forceinline__ void mma16816(float* d, const uint32_t* a,
                                         const uint32_t* b) {
    asm volatile(
        "mma.sync.aligned.m16n8k16.row.col.f32.bf16.bf16.f32 "
        "{%0,%1,%2,%3}, {%4,%5,%6,%7}, {%8,%9}, {%0,%1,%2,%3};"
        : "+f"(d[0]), "+f"(d[1]), "+f"(d[2]), "+f"(d[3])
        : "r"(a[0]), "r"(a[1]), "r"(a[2]), "r"(a[3]), "r"(b[0]), "r"(b[1]));
}

__device__ __forceinline__ void cp16(uint32_t s, const void* g) {
    asm volatile("cp.async.cg.shared.global [%0], [%1], 16;"
                 :: "r"(s), "l"(__cvta_generic_to_global(g)));
}
#define CP_COMMIT() asm volatile("cp.async.commit_group;" ::: "memory")
#define CP_WAIT1()  asm volatile("cp.async.wait_group 1;" ::: "memory")

// ---------------------------------------------------------------------------
// K1: normalize prototypes over C, split to bf16 hi/lo, reorder [i][a][c]
// ---------------------------------------------------------------------------
__global__ void k1_norm_proto(const float* __restrict__ proto) {
    int p    = blockIdx.x * 8 + (threadIdx.x >> 5);
    int lane = threadIdx.x & 31;
    if (p >= PP) return;
    float v0 = proto[p * CC + lane];
    float v1 = proto[p * CC + lane + 32];
    float ss = v0 * v0 + v1 * v1;
    #pragma unroll
    for (int o = 16; o; o >>= 1) ss += __shfl_xor_sync(0xffffffffu, ss, o);
    float sc = 1.0f / fmaxf(sqrtf(ss), 1e-12f);
    int i = p % NPROT, a = p / NPROT;
    size_t base = (size_t)(i * NCLS + a) * CC;
    float w0 = v0 * sc, w1 = v1 * sc;
    __nv_bfloat16 h0 = __float2bfloat16(w0);
    __nv_bfloat16 h1 = __float2bfloat16(w1);
    g_ph[base + lane]      = h0;
    g_ph[base + lane + 32] = h1;
    g_pl[base + lane]      = __float2bfloat16(w0 - __bfloat162float(h0));
    g_pl[base + lane + 32] = __float2bfloat16(w1 - __bfloat162float(h1));
}

// ---------------------------------------------------------------------------
// K2: normalize conv_features over C, split to bf16 hi/lo, reorder [i][b][c]
// ---------------------------------------------------------------------------
__global__ void k2_norm_x(const float* __restrict__ conv) {
    __shared__ float s[CC * 41];
    __shared__ float rn[WW];
    int b = blockIdx.x;
    int t = threadIdx.x;             // 256
    const float* src = conv + (size_t)b * (CC * WW);
    for (int e = t; e < CC * WW; e += 256) {
        int c = e / WW, w = e % WW;
        s[c * 41 + w] = src[e];
    }
    __syncthreads();
    if (t < WW) {
        float ss = 0.0f;
        #pragma unroll
        for (int c = 0; c < CC; ++c) { float v = s[c * 41 + t]; ss += v * v; }
        rn[t] = 1.0f / fmaxf(sqrtf(ss), 1e-12f);
    }
    __syncthreads();
    for (int e = t; e < WW * CC; e += 256) {
        int i = e / CC, c = e % CC;
        float v = s[c * 41 + i] * rn[i];
        __nv_bfloat16 h = __float2bfloat16(v);
        size_t idx = ((size_t)i * BB + b) * CC + c;
        g_xh[idx] = h;
        g_xl[idx] = __float2bfloat16(v - __bfloat162float(h));
    }
}

// ---------------------------------------------------------------------------
// K3 fused: per CTA a 128(b) x 32(a) output block, looping all 40 i with
// cp.async double-buffered operand tiles.  sim = Xh*Ph + Xh*Pl + Xl*Ph.
// i processed in chunks of 8 held in registers; each thread then writes
// 8 consecutive i per (b,a) pair = one full 32B sector -> no staging pass.
// Also accumulates S_n(b) across all i -> g_acc.
// ---------------------------------------------------------------------------
// Per-buffer smem layout (SW128 swizzle, 128B rows):
//   AH 0 (16KB) | AL 16384 (16KB) | BH 32768 (4KB) | BL 36864 (4KB)
#define BUF_STRIDE 40960
#define OFF_AL_ 16384
#define OFF_BH_ 32768
#define OFF_BL_ 36864
#define K3_SMEM (2 * BUF_STRIDE)   // 81920

extern __shared__ __align__(1024) char sm3[];

__device__ __forceinline__ void load_tiles(uint32_t sb, int i, int b0, int a0,
                                           int t) {
    uint32_t base = sb + (uint32_t)(i & 1) * BUF_STRIDE;
    const char* Ah = (const char*)(g_xh + ((size_t)i * BB + b0) * CC);
    const char* Al = (const char*)(g_xl + ((size_t)i * BB + b0) * CC);
    #pragma unroll
    for (int j = 0; j < 2; ++j) {
        int chunk = t + j * 512;         // 0..1023
        int row = chunk >> 3, c16 = chunk & 7;
        uint32_t sw = (uint32_t)(row * 128 + ((c16 ^ (row & 7)) * 16));
        cp16(base + sw, Ah + chunk * 16);
        cp16(base + OFF_AL_ + sw, Al + chunk * 16);
    }
    if (t < 256) {
        const char* Bh = (const char*)(g_ph + ((size_t)i * NCLS + a0) * CC);
        int row = t >> 3, c16 = t & 7;
        uint32_t sw = (uint32_t)(row * 128 + ((c16 ^ (row & 7)) * 16));
        cp16(base + OFF_BH_ + sw, Bh + t * 16);
    } else {
        const char* Bl = (const char*)(g_pl + ((size_t)i * NCLS + a0) * CC);
        int t2 = t - 256;
        int row = t2 >> 3, c16 = t2 & 7;
        uint32_t sw = (uint32_t)(row * 128 + ((c16 ^ (row & 7)) * 16));
        cp16(base + OFF_BL_ + sw, Bl + t2 * 16);
    }
}

__device__ __forceinline__ void pass8(uint32_t aBase, uint32_t bBase,
                                      const int* colA, const int* colB,
                                      float (&acc)[2][4]) {
    #pragma unroll
    for (int ks = 0; ks < 4; ++ks) {
        uint32_t a[4], bq[4];
        LDSM_X4(a, aBase + colA[ks]);
        LDSM_X4(bq, bBase + colB[ks]);
        mma16816(acc[0], a, bq);
        mma16816(acc[1], a, bq + 2);
    }
}

__global__ __launch_bounds__(512, 1) void k3_fused(float* __restrict__ out_md) {
    uint32_t sb = smem_to_u32(sm3);
    const int t    = threadIdx.x;
    const int w    = t >> 5;
    const int lane = t & 31;
    const int a0 = blockIdx.x * 32;
    const int b0 = blockIdx.y * 128;

    // Warp tile: 16 warps, each 16(m) x 16(n) of the 128x32 per-i block.
    const int m0w = (w & 7) * 16;
    const int n0w = (w >> 3) * 16;
    const int lane16 = lane & 15;
    const int swz = lane & 7;

    // A ldmatrix.x4: R = m0w + lane16, k-chunk base CA0 = lane>>4
    const int R   = m0w + lane16;
    const int CA0 = lane >> 4;
    // B ldmatrix.x4 (two n-tiles): groups g = lane>>3
    const int g   = lane >> 3;
    const int NB  = n0w + (g >> 1) * 8 + (lane & 7);
    const int CB0 = g & 1;

    int colA[4], colB[4];
    #pragma unroll
    for (int ks = 0; ks < 4; ++ks) {
        colA[ks] = ((CA0 + 2 * ks) ^ swz) * 16;
        colB[ks] = ((CB0 + 2 * ks) ^ swz) * 16;
    }
    const uint32_t aRow = (uint32_t)(R * 128);
    const uint32_t bRow = (uint32_t)(NB * 128);

    // Output coords per thread (8 (b,a) pairs via nt x q)
    const int qr = lane >> 2;
    const int qc = (lane & 3) * 2;

    float ssum[2][4];
    #pragma unroll
    for (int nt = 0; nt < 2; ++nt)
        #pragma unroll
        for (int q = 0; q < 4; ++q) ssum[nt][q] = 0.0f;

    load_tiles(sb, 0, b0, a0, t);
    CP_COMMIT();

    #pragma unroll 1
    for (int c = 0; c < 5; ++c) {
        float acc[8][2][4];
        #pragma unroll
        for (int il = 0; il < 8; ++il)
            #pragma unroll
            for (int nt = 0; nt < 2; ++nt)
                #pragma unroll
                for (int q = 0; q < 4; ++q) acc[il][nt][q] = 0.0f;

        #pragma unroll
        for (int il = 0; il < 8; ++il) {
            const int i = c * 8 + il;
            if (i + 1 < NPROT) load_tiles(sb, i + 1, b0, a0, t);
            CP_COMMIT();
            CP_WAIT1();
            __syncthreads();

            const uint32_t bo = sb + (uint32_t)(i & 1) * BUF_STRIDE;
            pass8(bo + aRow,            bo + OFF_BH_ + bRow, colA, colB, acc[il]); // hh
            pass8(bo + aRow,            bo + OFF_BL_ + bRow, colA, colB, acc[il]); // hl
            pass8(bo + OFF_AL_ + aRow,  bo + OFF_BH_ + bRow, colA, colB, acc[il]); // lh
            __syncthreads();
        }

        // Write chunk: for each (b,a) pair, 8 consecutive i -> 2x STG.128
        #pragma unroll
        for (int nt = 0; nt < 2; ++nt) {
            #pragma unroll
            for (int q = 0; q < 4; ++q) {
                int brow = b0 + m0w + qr + ((q >> 1) << 3);
                int aCls = a0 + n0w + nt * 8 + qc + (q & 1);
                float* p = out_md + (size_t)brow * PP + aCls * NPROT + c * 8;
                *(float4*)p = make_float4(-acc[0][nt][q], -acc[1][nt][q],
                                          -acc[2][nt][q], -acc[3][nt][q]);
                *(float4*)(p + 4) = make_float4(-acc[4][nt][q], -acc[5][nt][q],
                                                -acc[6][nt][q], -acc[7][nt][q]);
                ssum[nt][q] += (acc[0][nt][q] + acc[1][nt][q])
                             + (acc[2][nt][q] + acc[3][nt][q])
                             + (acc[4][nt][q] + acc[5][nt][q])
                             + (acc[6][nt][q] + acc[7][nt][q]);
            }
        }
    }

    // S_n(b): unique writer per (b, class)
    #pragma unroll
    for (int nt = 0; nt < 2; ++nt) {
        #pragma unroll
        for (int q = 0; q < 4; ++q) {
            int brow = b0 + m0w + qr + ((q >> 1) << 3);
            int aCls = a0 + n0w + nt * 8 + qc + (q & 1);
            g_acc[brow * NCLS + aCls] = ssum[nt][q];
        }
    }
}

// ---------------------------------------------------------------------------
// K5: logits[b][n] = 1.5 * S_n(b) - 0.5 * sum_n S_n(b)
// ---------------------------------------------------------------------------
__global__ void k5_logits(float* __restrict__ out_logits) {
    __shared__ float warpsum[16];
    __shared__ float stot;
    int b = blockIdx.x;
    int t = threadIdx.x;             // 512
    float v = g_acc[b * NCLS + t];
    float sx = v;
    #pragma unroll
    for (int o = 16; o; o >>= 1) sx += __shfl_xor_sync(0xffffffffu, sx, o);
    if ((t & 31) == 0) warpsum[t >> 5] = sx;
    __syncthreads();
    if (t == 0) {
        float x = 0.0f;
        #pragma unroll
        for (int w = 0; w < 16; ++w) x += warpsum[w];
        stot = x;
    }
    __syncthreads();
    out_logits[b * NCLS + t] = 1.5f * v - 0.5f * stot;
}

// ---------------------------------------------------------------------------
// Launch
// ---------------------------------------------------------------------------
extern "C" void kernel_launch(void* const* d_in, const int* in_sizes, int n_in,
                              void* d_out, int out_size) {
    (void)in_sizes; (void)n_in; (void)out_size;
    const float* conv  = (const float*)d_in[0];
    const float* proto = (const float*)d_in[1];
    float* out        = (float*)d_out;
    float* out_logits = out;
    float* out_md     = out + (size_t)BB * NCLS;

    cudaFuncSetAttribute(k3_fused, cudaFuncAttributeMaxDynamicSharedMemorySize,
                         K3_SMEM);

    k1_norm_proto<<<PP / 8, 256>>>(proto);
    k2_norm_x<<<BB, 256>>>(conv);
    dim3 g3(NCLS / 32, BB / 128);        // 16 x 8 = 128 CTAs
    k3_fused<<<g3, 512, K3_SMEM>>>(out_md);
    k5_logits<<<BB, 512>>>(out_logits);
}

// round 16
// speedup vs baseline: 1.0025x; 1.0025x over previous
#include <cuda_runtime.h>
#include <cuda_bf16.h>
#include <cstdint>

// Problem constants
#define BB      1024
#define CC      64
#define WW      40
#define NPROT   40
#define NCLS    512
#define PP      (NPROT * NCLS)   // 20480

// ---------------------------------------------------------------------------
// Scratch (device globals; no dynamic allocation)
// ---------------------------------------------------------------------------
__device__ __align__(16) __nv_bfloat16 g_xh[NPROT * BB * CC];    // [i][b][c] hi
__device__ __align__(16) __nv_bfloat16 g_xl[NPROT * BB * CC];    // [i][b][c] lo
__device__ __align__(16) __nv_bfloat16 g_ph[NPROT * NCLS * CC];  // [i][a][c] hi
__device__ __align__(16) __nv_bfloat16 g_pl[NPROT * NCLS * CC];  // [i][a][c] lo
__device__ __align__(16) float g_acc[BB * NCLS];                 // S_n(b)

// ---------------------------------------------------------------------------
// Portable helpers (compute_103-safe: ldmatrix + mma.sync + cp.async)
// ---------------------------------------------------------------------------
__device__ __forceinline__ uint32_t smem_to_u32(const void* p) {
    uint32_t a;
    asm("{ .reg .u64 t; cvta.to.shared.u64 t, %1; cvt.u32.u64 %0, t; }"
        : "=r"(a) : "l"(p));
    return a;
}

#define LDSM_X4(r, addr) \
    asm volatile("ldmatrix.sync.aligned.m8n8.x4.shared.b16 {%0,%1,%2,%3}, [%4];" \
                 : "=r"((r)[0]), "=r"((r)[1]), "=r"((r)[2]), "=r"((r)[3]) \
                 : "r"(addr))

__device__ __forceinline__ void mma16816(float* d, const uint32_t* a,
                                         const uint32_t* b) {
    asm volatile(
        "mma.sync.aligned.m16n8k16.row.col.f32.bf16.bf16.f32 "
        "{%0,%1,%2,%3}, {%4,%5,%6,%7}, {%8,%9}, {%0,%1,%2,%3};"
        : "+f"(d[0]), "+f"(d[1]), "+f"(d[2]), "+f"(d[3])
        : "r"(a[0]), "r"(a[1]), "r"(a[2]), "r"(a[3]), "r"(b[0]), "r"(b[1]));
}

__device__ __forceinline__ void cp16(uint32_t s, const void* g) {
    asm volatile("cp.async.cg.shared.global [%0], [%1], 16;"
                 :: "r"(s), "l"(__cvta_generic_to_global(g)));
}
#define CP_COMMIT() asm volatile("cp.async.commit_group;" ::: "memory")
#define CP_WAIT1()  asm volatile("cp.async.wait_group 1;" ::: "memory")

// ---------------------------------------------------------------------------
// K1: normalize prototypes over C, split to bf16 hi/lo, reorder [i][a][c]
// ---------------------------------------------------------------------------
__global__ void k1_norm_proto(const float* __restrict__ proto) {
    int p    = blockIdx.x * 8 + (threadIdx.x >> 5);
    int lane = threadIdx.x & 31;
    if (p >= PP) return;
    float v0 = proto[p * CC + lane];
    float v1 = proto[p * CC + lane + 32];
    float ss = v0 * v0 + v1 * v1;
    #pragma unroll
    for (int o = 16; o; o >>= 1) ss += __shfl_xor_sync(0xffffffffu, ss, o);
    float sc = 1.0f / fmaxf(sqrtf(ss), 1e-12f);
    int i = p % NPROT, a = p / NPROT;
    size_t base = (size_t)(i * NCLS + a) * CC;
    float w0 = v0 * sc, w1 = v1 * sc;
    __nv_bfloat16 h0 = __float2bfloat16(w0);
    __nv_bfloat16 h1 = __float2bfloat16(w1);
    g_ph[base + lane]      = h0;
    g_ph[base + lane + 32] = h1;
    g_pl[base + lane]      = __float2bfloat16(w0 - __bfloat162float(h0));
    g_pl[base + lane + 32] = __float2bfloat16(w1 - __bfloat162float(h1));
}

// ---------------------------------------------------------------------------
// K2: normalize conv_features over C, split to bf16 hi/lo, reorder [i][b][c]
// ---------------------------------------------------------------------------
__global__ void k2_norm_x(const float* __restrict__ conv) {
    __shared__ float s[CC * 41];
    __shared__ float rn[WW];
    int b = blockIdx.x;
    int t = threadIdx.x;             // 256
    const float* src = conv + (size_t)b * (CC * WW);
    for (int e = t; e < CC * WW; e += 256) {
        int c = e / WW, w = e % WW;
        s[c * 41 + w] = src[e];
    }
    __syncthreads();
    if (t < WW) {
        float ss = 0.0f;
        #pragma unroll
        for (int c = 0; c < CC; ++c) { float v = s[c * 41 + t]; ss += v * v; }
        rn[t] = 1.0f / fmaxf(sqrtf(ss), 1e-12f);
    }
    __syncthreads();
    for (int e = t; e < WW * CC; e += 256) {
        int i = e / CC, c = e % CC;
        float v = s[c * 41 + i] * rn[i];
        __nv_bfloat16 h = __float2bfloat16(v);
        size_t idx = ((size_t)i * BB + b) * CC + c;
        g_xh[idx] = h;
        g_xl[idx] = __float2bfloat16(v - __bfloat162float(h));
    }
}

// ---------------------------------------------------------------------------
// K3 fused v2: per CTA 64(b) x 32(a), loop over all 40 i (double-buffered
// cp.async).  sim = Xh*Ph + Xh*Pl + Xl*Ph.  i chunked by 4 in registers;
// each thread stores a float4 of 4 consecutive i per (b,a) -> direct,
// aligned output in p = 40a + i layout.  S_n(b) accumulated in registers.
// 256 threads, 48KB smem -> 2 CTA/SM; grid 16x16 = 256 CTAs.
// ---------------------------------------------------------------------------
// Per-buffer smem layout (swizzled 128B rows):
//   AH 0 (8KB) | AL 8192 (8KB) | BH 16384 (4KB) | BL 20480 (4KB)
#define OFF_AL_ 8192
#define OFF_BH_ 16384
#define OFF_BL_ 20480
#define BUF_STRIDE 24576
#define K3_SMEM (2 * BUF_STRIDE)   // 49152

extern __shared__ __align__(1024) char sm3[];

__device__ __forceinline__ void load_tiles(uint32_t sb, int i, int b0, int a0,
                                           int t) {
    uint32_t base = sb + (uint32_t)(i & 1) * BUF_STRIDE;
    const char* Ah = (const char*)(g_xh + ((size_t)i * BB + b0) * CC);
    const char* Al = (const char*)(g_xl + ((size_t)i * BB + b0) * CC);
    #pragma unroll
    for (int j = 0; j < 2; ++j) {
        int chunk = t + j * 256;         // 0..511 (64 rows x 8)
        int row = chunk >> 3, c16 = chunk & 7;
        uint32_t sw = (uint32_t)(row * 128 + ((c16 ^ (row & 7)) * 16));
        cp16(base + sw, Ah + chunk * 16);
        cp16(base + OFF_AL_ + sw, Al + chunk * 16);
    }
    {
        const char* Bh = (const char*)(g_ph + ((size_t)i * NCLS + a0) * CC);
        const char* Bl = (const char*)(g_pl + ((size_t)i * NCLS + a0) * CC);
        int row = t >> 3, c16 = t & 7;   // t 0..255 = 32 rows x 8
        uint32_t sw = (uint32_t)(row * 128 + ((c16 ^ (row & 7)) * 16));
        cp16(base + OFF_BH_ + sw, Bh + t * 16);
        cp16(base + OFF_BL_ + sw, Bl + t * 16);
    }
}

__device__ __forceinline__ void pass16(uint32_t aBase, uint32_t bBase,
                                       const int* colA, const int* colB,
                                       float (&acc)[2][4]) {
    #pragma unroll
    for (int ks = 0; ks < 4; ++ks) {
        uint32_t a[4], bq[4];
        LDSM_X4(a, aBase + colA[ks]);
        LDSM_X4(bq, bBase + colB[ks]);
        mma16816(acc[0], a, bq);
        mma16816(acc[1], a, bq + 2);
    }
}

__global__ __launch_bounds__(256, 2) void k3_fused(float* __restrict__ out_md) {
    uint32_t sb = smem_to_u32(sm3);
    const int t    = threadIdx.x;
    const int w    = t >> 5;
    const int lane = t & 31;
    const int a0 = blockIdx.x * 32;
    const int b0 = blockIdx.y * 64;

    // 8 warps: 4 m-tiles (16) x 2 n-tiles (16)
    const int m0w = (w & 3) * 16;
    const int n0w = (w >> 2) * 16;
    const int lane16 = lane & 15;
    const int swz = lane & 7;

    // A ldmatrix.x4 (proven R7/R12 pattern)
    const int R   = m0w + lane16;
    const int CA0 = lane >> 4;
    // B ldmatrix.x4 covering two n-tiles of 8
    const int g   = lane >> 3;
    const int NB  = n0w + (g >> 1) * 8 + (lane & 7);
    const int CB0 = g & 1;

    int colA[4], colB[4];
    #pragma unroll
    for (int ks = 0; ks < 4; ++ks) {
        colA[ks] = ((CA0 + 2 * ks) ^ swz) * 16;
        colB[ks] = ((CB0 + 2 * ks) ^ swz) * 16;
    }
    const uint32_t aRow = (uint32_t)(R * 128);
    const uint32_t bRow = (uint32_t)(NB * 128);

    // Output coords (8 (b,a) pairs per thread via nt x q)
    const int qr = lane >> 2;
    const int qc = (lane & 3) * 2;

    float ssum[2][4];
    #pragma unroll
    for (int nt = 0; nt < 2; ++nt)
        #pragma unroll
        for (int q = 0; q < 4; ++q) ssum[nt][q] = 0.0f;

    load_tiles(sb, 0, b0, a0, t);
    CP_COMMIT();

    #pragma unroll 1
    for (int c = 0; c < 10; ++c) {
        float acc[4][2][4];
        #pragma unroll
        for (int il = 0; il < 4; ++il)
            #pragma unroll
            for (int nt = 0; nt < 2; ++nt)
                #pragma unroll
                for (int q = 0; q < 4; ++q) acc[il][nt][q] = 0.0f;

        #pragma unroll
        for (int il = 0; il < 4; ++il) {
            const int i = c * 4 + il;
            if (i + 1 < NPROT) load_tiles(sb, i + 1, b0, a0, t);
            CP_COMMIT();
            CP_WAIT1();
            __syncthreads();

            const uint32_t bo = sb + (uint32_t)(i & 1) * BUF_STRIDE;
            pass16(bo + aRow,           bo + OFF_BH_ + bRow, colA, colB, acc[il]); // hh
            pass16(bo + aRow,           bo + OFF_BL_ + bRow, colA, colB, acc[il]); // hl
            pass16(bo + OFF_AL_ + aRow, bo + OFF_BH_ + bRow, colA, colB, acc[il]); // lh
            __syncthreads();
        }

        // Store chunk: per (b,a) pair, 4 consecutive i -> one STG.128
        #pragma unroll
        for (int nt = 0; nt < 2; ++nt) {
            #pragma unroll
            for (int q = 0; q < 4; ++q) {
                int brow = b0 + m0w + qr + ((q >> 1) << 3);
                int aCls = a0 + n0w + nt * 8 + qc + (q & 1);
                float* p = out_md + (size_t)brow * PP + aCls * NPROT + c * 4;
                *(float4*)p = make_float4(-acc[0][nt][q], -acc[1][nt][q],
                                          -acc[2][nt][q], -acc[3][nt][q]);
                ssum[nt][q] += (acc[0][nt][q] + acc[1][nt][q])
                             + (acc[2][nt][q] + acc[3][nt][q]);
            }
        }
    }

    // S_n(b): unique writer per (b, class)
    #pragma unroll
    for (int nt = 0; nt < 2; ++nt) {
        #pragma unroll
        for (int q = 0; q < 4; ++q) {
            int brow = b0 + m0w + qr + ((q >> 1) << 3);
            int aCls = a0 + n0w + nt * 8 + qc + (q & 1);
            g_acc[brow * NCLS + aCls] = ssum[nt][q];
        }
    }
}

// ---------------------------------------------------------------------------
// K5: logits[b][n] = 1.5 * S_n(b) - 0.5 * sum_n S_n(b)
// ---------------------------------------------------------------------------
__global__ void k5_logits(float* __restrict__ out_logits) {
    __shared__ float warpsum[16];
    __shared__ float stot;
    int b = blockIdx.x;
    int t = threadIdx.x;             // 512
    float v = g_acc[b * NCLS + t];
    float sx = v;
    #pragma unroll
    for (int o = 16; o; o >>= 1) sx += __shfl_xor_sync(0xffffffffu, sx, o);
    if ((t & 31) == 0) warpsum[t >> 5] = sx;
    __syncthreads();
    if (t == 0) {
        float x = 0.0f;
        #pragma unroll
        for (int w = 0; w < 16; ++w) x += warpsum[w];
        stot = x;
    }
    __syncthreads();
    out_logits[b * NCLS + t] = 1.5f * v - 0.5f * stot;
}

// ---------------------------------------------------------------------------
// Launch
// ---------------------------------------------------------------------------
extern "C" void kernel_launch(void* const* d_in, const int* in_sizes, int n_in,
                              void* d_out, int out_size) {
    (void)in_sizes; (void)n_in; (void)out_size;
    const float* conv  = (const float*)d_in[0];
    const float* proto = (const float*)d_in[1];
    float* out        = (float*)d_out;
    float* out_logits = out;
    float* out_md     = out + (size_t)BB * NCLS;

    cudaFuncSetAttribute(k3_fused, cudaFuncAttributeMaxDynamicSharedMemorySize,
                         K3_SMEM);

    k1_norm_proto<<<PP / 8, 256>>>(proto);
    k2_norm_x<<<BB, 256>>>(conv);
    dim3 g3(NCLS / 32, BB / 64);         // 16 x 16 = 256 CTAs
    k3_fused<<<g3, 256, K3_SMEM>>>(out_md);
    k5_logits<<<BB, 512>>>(out_logits);
}